// round 11
// baseline (speedup 1.0000x reference)
#include <cuda_runtime.h>
#include <cuda_fp16.h>
#include <cstdint>

#define NF 128
#define NH 64
#define MAXN 50000
#define MAXE 800000

// Scratch (allocation-free rule: __device__ globals)
__device__ __half2 g_zh[(size_t)MAXN * (NH / 2)];   // 6.4 MB, z in fp16
__device__ float g_sd[MAXN];
__device__ float g_ss[MAXN];
__device__ int   g_cnt[MAXN];
__device__ int   g_rowstart[MAXN];
__device__ int   g_cursor[MAXN];
__device__ int   g_bsum[1024];
__device__ int4  g_csr[MAXE];              // {src, eidx, h_bits, 0}
__device__ int   g_is32;

// ---------------------------------------------------------------------------
// zero cnt + dtype probe in one launch (block 0 probes).
__global__ void zero_detect_kernel(const int* __restrict__ w, int nelem, int n_nodes) {
    int i = blockIdx.x * blockDim.x + threadIdx.x;
    if (i < n_nodes) g_cnt[i] = 0;
    if (i == 0) g_is32 = 0;
    if (blockIdx.x == gridDim.x - 1) {   // runs after i==0's write? No ordering —
        // use a separate flag approach: probe writes only if nonzero found, init
        // g_is32 via i==0 is racy with the probe. Probe sets 1 only; init to 0
        // must happen first. Solve: probe accumulates into g_is32 with atomicOr
        // AFTER a __threadfence? Simpler: dedicated value below.
    }
}

// dtype probe (separate tiny kernel to keep ordering clean).
__global__ void detect_kernel(const int* __restrict__ w, int nelem) {
    int found = 0;
    int lim = nelem / 2;
    if (lim > 4096) lim = 4096;
    for (int i = threadIdx.x; i < lim; i += 256)
        found |= w[2 * i + 1];
    if (__syncthreads_or(found) && threadIdx.x == 0) g_is32 = 1;
}

// Histogram straight from edge_index dst row (no int32 intermediate), 4/thread.
__global__ void hist_kernel(const void* __restrict__ ei, int E) {
    int t = blockIdx.x * blockDim.x + threadIdx.x;
    int base = t * 4;
    if (base >= E) return;
    if (base + 3 < E && (base & 3) == 0) {
        int4 d4;
        if (g_is32) {
            d4 = reinterpret_cast<const int4*>(ei)[base >> 2];
        } else {
            const longlong2* p = (const longlong2*)ei;
            longlong2 a0 = p[base >> 1];
            longlong2 a1 = p[(base >> 1) + 1];
            d4 = make_int4((int)a0.x, (int)a0.y, (int)a1.x, (int)a1.y);
        }
        atomicAdd(&g_cnt[d4.x], 1);
        atomicAdd(&g_cnt[d4.y], 1);
        atomicAdd(&g_cnt[d4.z], 1);
        atomicAdd(&g_cnt[d4.w], 1);
    } else {
        for (int i = base; i < E && i < base + 4; i++) {
            int d = g_is32 ? ((const int*)ei)[i] : (int)((const long long*)ei)[i];
            atomicAdd(&g_cnt[d], 1);
        }
    }
}

// ---------------------------------------------------------------------------
// Exclusive scan of g_cnt -> g_rowstart.
__global__ void scanA(int n) {
    __shared__ int s[256];
    int t = threadIdx.x, i = blockIdx.x * 256 + t;
    s[t] = (i < n) ? g_cnt[i] : 0;
    __syncthreads();
    for (int off = 128; off; off >>= 1) {
        if (t < off) s[t] += s[t + off];
        __syncthreads();
    }
    if (t == 0) g_bsum[blockIdx.x] = s[0];
}

__global__ void scanB(int nb) {
    __shared__ int s[256];
    int t = threadIdx.x;
    int v = (t < nb) ? g_bsum[t] : 0;
    s[t] = v; __syncthreads();
    for (int off = 1; off < 256; off <<= 1) {
        int a = (t >= off) ? s[t - off] : 0;
        __syncthreads();
        s[t] += a;
        __syncthreads();
    }
    if (t < nb) g_bsum[t] = s[t] - v;
}

__global__ void scanC(int n) {
    __shared__ int s[256];
    int t = threadIdx.x, i = blockIdx.x * 256 + t;
    int v = (i < n) ? g_cnt[i] : 0;
    s[t] = v; __syncthreads();
    for (int off = 1; off < 256; off <<= 1) {
        int a = (t >= off) ? s[t - off] : 0;
        __syncthreads();
        s[t] += a;
        __syncthreads();
    }
    if (i < n) {
        int start = g_bsum[blockIdx.x] + s[t] - v;
        g_rowstart[i] = start;
        g_cursor[i]   = start;
    }
}

// ---------------------------------------------------------------------------
// Register-tiled GEMM (round-2 proven config): 64x64 tile, 4x4 per thread,
// fused score reduction; z stored as fp16 half2.
__global__ void __launch_bounds__(256) gemm_kernel(
    const float* __restrict__ x, const float* __restrict__ W,
    const float* __restrict__ aw, int n_nodes)
{
    __shared__ float xs[64][64];
    __shared__ float Ws[64][64];

    const int tid = threadIdx.x;
    const int tx  = tid & 15;
    const int ty  = tid >> 4;
    const int row0 = blockIdx.x * 64;

    float acc[4][4];
#pragma unroll
    for (int i = 0; i < 4; i++)
#pragma unroll
        for (int j = 0; j < 4; j++) acc[i][j] = 0.f;

    for (int kc = 0; kc < NF; kc += 64) {
#pragma unroll
        for (int it = 0; it < 4; it++) {
            int i = tid + it * 256;
            int r = i >> 4, q = (i & 15) << 2;
            int row = row0 + r;
            float4 v = make_float4(0.f, 0.f, 0.f, 0.f);
            if (row < n_nodes)
                v = *reinterpret_cast<const float4*>(&x[(size_t)row * NF + kc + q]);
            *reinterpret_cast<float4*>(&xs[r][q]) = v;
        }
#pragma unroll
        for (int it = 0; it < 4; it++) {
            int i = tid + it * 256;
            int k = i >> 4, q = (i & 15) << 2;
            *reinterpret_cast<float4*>(&Ws[k][q]) =
                *reinterpret_cast<const float4*>(&W[(size_t)(kc + k) * NH + q]);
        }
        __syncthreads();

#pragma unroll
        for (int k = 0; k < 64; k++) {
            float4 wv = *reinterpret_cast<const float4*>(&Ws[k][tx << 2]);
            float x0 = xs[(ty << 2) + 0][k];
            float x1 = xs[(ty << 2) + 1][k];
            float x2 = xs[(ty << 2) + 2][k];
            float x3 = xs[(ty << 2) + 3][k];
            acc[0][0] = fmaf(x0, wv.x, acc[0][0]); acc[0][1] = fmaf(x0, wv.y, acc[0][1]);
            acc[0][2] = fmaf(x0, wv.z, acc[0][2]); acc[0][3] = fmaf(x0, wv.w, acc[0][3]);
            acc[1][0] = fmaf(x1, wv.x, acc[1][0]); acc[1][1] = fmaf(x1, wv.y, acc[1][1]);
            acc[1][2] = fmaf(x1, wv.z, acc[1][2]); acc[1][3] = fmaf(x1, wv.w, acc[1][3]);
            acc[2][0] = fmaf(x2, wv.x, acc[2][0]); acc[2][1] = fmaf(x2, wv.y, acc[2][1]);
            acc[2][2] = fmaf(x2, wv.z, acc[2][2]); acc[2][3] = fmaf(x2, wv.w, acc[2][3]);
            acc[3][0] = fmaf(x3, wv.x, acc[3][0]); acc[3][1] = fmaf(x3, wv.y, acc[3][1]);
            acc[3][2] = fmaf(x3, wv.z, acc[3][2]); acc[3][3] = fmaf(x3, wv.w, acc[3][3]);
        }
        __syncthreads();
    }

    const float4 a1 = *reinterpret_cast<const float4*>(&aw[tx << 2]);
    const float4 a2 = *reinterpret_cast<const float4*>(&aw[NH + (tx << 2)]);

#pragma unroll
    for (int i = 0; i < 4; i++) {
        int row = row0 + (ty << 2) + i;
        float sd = acc[i][0] * a1.x + acc[i][1] * a1.y + acc[i][2] * a1.z + acc[i][3] * a1.w;
        float ss = acc[i][0] * a2.x + acc[i][1] * a2.y + acc[i][2] * a2.z + acc[i][3] * a2.w;
#pragma unroll
        for (int off = 8; off; off >>= 1) {
            sd += __shfl_down_sync(0xffffffffu, sd, off, 16);
            ss += __shfl_down_sync(0xffffffffu, ss, off, 16);
        }
        if (row < n_nodes) {
            __half2 hp[2];
            hp[0] = __floats2half2_rn(acc[i][0], acc[i][1]);
            hp[1] = __floats2half2_rn(acc[i][2], acc[i][3]);
            *reinterpret_cast<float2*>(&g_zh[(size_t)row * 32 + (tx << 1)]) =
                *reinterpret_cast<const float2*>(hp);
            if (tx == 0) { g_sd[row] = sd; g_ss[row] = ss; }
        }
    }
}

// ---------------------------------------------------------------------------
// Per-edge score + CSR scatter, reading edge_index directly, 4 edges/thread.
__global__ void edge_scatter_kernel(const void* __restrict__ ei,
                                    const float* __restrict__ ab, int E)
{
    int t = blockIdx.x * blockDim.x + threadIdx.x;
    int base = t * 4;
    if (base >= E) return;
    float b = __ldg(ab);
    if (base + 3 < E && (base & 3) == 0) {
        int4 d4, s4;
        if (g_is32) {
            const int4* p = (const int4*)ei;
            d4 = p[base >> 2];
            s4 = p[(E + base) >> 2];
        } else {
            const longlong2* p = (const longlong2*)ei;
            longlong2 a0 = p[(base >> 1)];
            longlong2 a1 = p[(base >> 1) + 1];
            longlong2 b0 = p[((E + base) >> 1)];
            longlong2 b1 = p[((E + base) >> 1) + 1];
            d4 = make_int4((int)a0.x, (int)a0.y, (int)a1.x, (int)a1.y);
            s4 = make_int4((int)b0.x, (int)b0.y, (int)b1.x, (int)b1.y);
        }
        int dd[4] = {d4.x, d4.y, d4.z, d4.w};
        int ssr[4] = {s4.x, s4.y, s4.z, s4.w};
#pragma unroll
        for (int j = 0; j < 4; j++) {
            float h = g_sd[dd[j]] + g_ss[ssr[j]] + b;
            h = (h >= 0.f) ? h : 0.05f * h;
            h = expf(h);
            int pos = atomicAdd(&g_cursor[dd[j]], 1);
            g_csr[pos] = make_int4(ssr[j], base + j, __float_as_int(h), 0);
        }
    } else {
        for (int i = base; i < E && i < base + 4; i++) {
            int d, s;
            if (g_is32) {
                const int* p = (const int*)ei;
                d = p[i]; s = p[E + i];
            } else {
                const long long* p = (const long long*)ei;
                d = (int)p[i]; s = (int)p[E + i];
            }
            float h = g_sd[d] + g_ss[s] + b;
            h = (h >= 0.f) ? h : 0.05f * h;
            h = expf(h);
            int pos = atomicAdd(&g_cursor[d], 1);
            g_csr[pos] = make_int4(s, i, __float_as_int(h), 0);
        }
    }
}

// ---------------------------------------------------------------------------
// One warp per dst node; deg-loop unrolled x4 with batched independent loads
// (MLP 8) since the phase is latency-bound, not bandwidth-bound.
__global__ void __launch_bounds__(256) aggregate_csr_kernel(
    float* __restrict__ out, float* __restrict__ alpha, int n_nodes)
{
    int w = (blockIdx.x * 256 + threadIdx.x) >> 5;
    int lane = threadIdx.x & 31;
    if (w >= n_nodes) return;

    int start = g_rowstart[w];
    int deg   = g_cnt[w];

    float2 acc = make_float2(0.f, 0.f);
    float hs = 0.f;
    int e = 0;
    for (; e + 4 <= deg; e += 4) {
        int4 n0 = g_csr[start + e];
        int4 n1 = g_csr[start + e + 1];
        int4 n2 = g_csr[start + e + 2];
        int4 n3 = g_csr[start + e + 3];
        __half2 z0 = g_zh[(size_t)n0.x * 32 + lane];
        __half2 z1 = g_zh[(size_t)n1.x * 32 + lane];
        __half2 z2 = g_zh[(size_t)n2.x * 32 + lane];
        __half2 z3 = g_zh[(size_t)n3.x * 32 + lane];
        float h0 = __int_as_float(n0.z), h1 = __int_as_float(n1.z);
        float h2 = __int_as_float(n2.z), h3 = __int_as_float(n3.z);
        hs += (h0 + h1) + (h2 + h3);
        float2 v0 = __half22float2(z0), v1 = __half22float2(z1);
        float2 v2 = __half22float2(z2), v3 = __half22float2(z3);
        acc.x = fmaf(h0, v0.x, acc.x); acc.y = fmaf(h0, v0.y, acc.y);
        acc.x = fmaf(h1, v1.x, acc.x); acc.y = fmaf(h1, v1.y, acc.y);
        acc.x = fmaf(h2, v2.x, acc.x); acc.y = fmaf(h2, v2.y, acc.y);
        acc.x = fmaf(h3, v3.x, acc.x); acc.y = fmaf(h3, v3.y, acc.y);
    }
    for (; e < deg; e++) {
        int4 ent = g_csr[start + e];
        float h = __int_as_float(ent.z);
        hs += h;
        float2 zv = __half22float2(g_zh[(size_t)ent.x * 32 + lane]);
        acc.x = fmaf(h, zv.x, acc.x);
        acc.y = fmaf(h, zv.y, acc.y);
    }
    float inv = (hs != 0.f) ? (1.f / hs) : 0.f;
    *reinterpret_cast<float2*>(&out[(size_t)w * NH + lane * 2]) =
        make_float2(acc.x * inv, acc.y * inv);

    for (int k = lane; k < deg; k += 32) {
        int4 ent = g_csr[start + k];            // L1 hit
        alpha[ent.y] = __int_as_float(ent.z) * inv;
    }
}

// ---------------------------------------------------------------------------
extern "C" void kernel_launch(void* const* d_in, const int* in_sizes, int n_in,
                              void* d_out, int out_size)
{
    const float* x  = (const float*)d_in[0];
    const void*  ei = d_in[1];
    const float* W  = (const float*)d_in[2];
    const float* aw = (const float*)d_in[3];
    const float* ab = (const float*)d_in[4];

    const int n_nodes = in_sizes[0] / NF;
    const int E       = in_sizes[1] / 2;
    const int nb      = (n_nodes + 255) / 256;

    float* out   = (float*)d_out;
    float* alpha = out + (size_t)n_nodes * NH;

    zero_detect_kernel<<<(n_nodes + 255) / 256, 256>>>((const int*)ei,
                                                       in_sizes[1], n_nodes);
    detect_kernel<<<1, 256>>>((const int*)ei, in_sizes[1]);
    hist_kernel<<<(E / 4 + 255) / 256, 256>>>(ei, E);

    gemm_kernel<<<(n_nodes + 63) / 64, 256>>>(x, W, aw, n_nodes);

    scanA<<<nb, 256>>>(n_nodes);
    scanB<<<1, 256>>>(nb);
    scanC<<<nb, 256>>>(n_nodes);

    edge_scatter_kernel<<<(E / 4 + 255) / 256, 256>>>(ei, ab, E);

    long long tot = (long long)n_nodes * 32;
    aggregate_csr_kernel<<<(int)((tot + 255) / 256), 256>>>(out, alpha, n_nodes);
}

// round 12
// speedup vs baseline: 1.0229x; 1.0229x over previous
#include <cuda_runtime.h>
#include <cuda_fp16.h>
#include <cstdint>

#define NF 128
#define NH 64
#define MAXN 50000
#define MAXE 800000

// Scratch (allocation-free rule: __device__ globals)
__device__ __half2 g_zh[(size_t)MAXN * (NH / 2)];   // 6.4 MB, z in fp16
__device__ float g_sd[MAXN];
__device__ float g_ss[MAXN];
__device__ int   g_dst[MAXE];
__device__ int   g_src[MAXE];
__device__ int   g_cnt[MAXN];
__device__ int   g_rowstart[MAXN];
__device__ int   g_cursor[MAXN];
__device__ int   g_bsum[1024];
__device__ int4  g_csr[MAXE];              // {src, eidx, h_bits, 0}
__device__ int   g_is32;

// ---------------------------------------------------------------------------
__global__ void zero_kernel(int n_nodes) {
    int i = blockIdx.x * blockDim.x + threadIdx.x;
    if (i < n_nodes) g_cnt[i] = 0;
    if (i == 0) g_is32 = 0;
}

// dtype probe: scan first 4096 odd words; int64 (<2^31 values) -> all zero.
__global__ void detect_kernel(const int* __restrict__ w, int nelem) {
    int found = 0;
    int lim = nelem / 2;
    if (lim > 4096) lim = 4096;
    for (int i = threadIdx.x; i < lim; i += 256)
        found |= w[2 * i + 1];
    if (__syncthreads_or(found) && threadIdx.x == 0) g_is32 = 1;
}

// Convert to int32 + histogram, 4 edges per thread, vector loads/stores.
__global__ void convert_kernel(const void* __restrict__ ei, int E) {
    int t = blockIdx.x * blockDim.x + threadIdx.x;
    int base = t * 4;
    if (base >= E) return;
    if (base + 3 < E && (E & 3) == 0) {
        int4 d4, s4;
        if (g_is32) {
            const int4* p = (const int4*)ei;
            d4 = p[base >> 2];
            s4 = p[(E + base) >> 2];
        } else {
            const longlong2* p = (const longlong2*)ei;
            longlong2 a0 = p[(base >> 1)];
            longlong2 a1 = p[(base >> 1) + 1];
            longlong2 b0 = p[((E + base) >> 1)];
            longlong2 b1 = p[((E + base) >> 1) + 1];
            d4 = make_int4((int)a0.x, (int)a0.y, (int)a1.x, (int)a1.y);
            s4 = make_int4((int)b0.x, (int)b0.y, (int)b1.x, (int)b1.y);
        }
        *reinterpret_cast<int4*>(&g_dst[base]) = d4;
        *reinterpret_cast<int4*>(&g_src[base]) = s4;
        atomicAdd(&g_cnt[d4.x], 1);
        atomicAdd(&g_cnt[d4.y], 1);
        atomicAdd(&g_cnt[d4.z], 1);
        atomicAdd(&g_cnt[d4.w], 1);
    } else {
        for (int i = base; i < E && i < base + 4; i++) {
            int d, s;
            if (g_is32) {
                const int* p = (const int*)ei;
                d = p[i]; s = p[E + i];
            } else {
                const long long* p = (const long long*)ei;
                d = (int)p[i]; s = (int)p[E + i];
            }
            g_dst[i] = d;
            g_src[i] = s;
            atomicAdd(&g_cnt[d], 1);
        }
    }
}

// ---------------------------------------------------------------------------
// Exclusive scan of g_cnt -> g_rowstart.
__global__ void scanA(int n) {
    __shared__ int s[256];
    int t = threadIdx.x, i = blockIdx.x * 256 + t;
    s[t] = (i < n) ? g_cnt[i] : 0;
    __syncthreads();
    for (int off = 128; off; off >>= 1) {
        if (t < off) s[t] += s[t + off];
        __syncthreads();
    }
    if (t == 0) g_bsum[blockIdx.x] = s[0];
}

__global__ void scanB(int nb) {
    __shared__ int s[256];
    int t = threadIdx.x;
    int v = (t < nb) ? g_bsum[t] : 0;
    s[t] = v; __syncthreads();
    for (int off = 1; off < 256; off <<= 1) {
        int a = (t >= off) ? s[t - off] : 0;
        __syncthreads();
        s[t] += a;
        __syncthreads();
    }
    if (t < nb) g_bsum[t] = s[t] - v;
}

__global__ void scanC(int n) {
    __shared__ int s[256];
    int t = threadIdx.x, i = blockIdx.x * 256 + t;
    int v = (i < n) ? g_cnt[i] : 0;
    s[t] = v; __syncthreads();
    for (int off = 1; off < 256; off <<= 1) {
        int a = (t >= off) ? s[t - off] : 0;
        __syncthreads();
        s[t] += a;
        __syncthreads();
    }
    if (i < n) {
        int start = g_bsum[blockIdx.x] + s[t] - v;
        g_rowstart[i] = start;
        g_cursor[i]   = start;
    }
}

// ---------------------------------------------------------------------------
// Register-tiled GEMM, k-vectorized x reads: per 4k, each thread does
// 4 x-LDS.128 + 4 W-LDS.128 feeding 64 FMAs (12 L1 wavefronts vs 24).
// xs/Ws padded to stride 68 so the two ty-half broadcast addresses hit
// different banks (272 mod 32 = 16).
#define TS 68

__global__ void __launch_bounds__(256) gemm_kernel(
    const float* __restrict__ x, const float* __restrict__ W,
    const float* __restrict__ aw, int n_nodes)
{
    __shared__ float xs[64 * TS];
    __shared__ float Ws[64 * TS];

    const int tid = threadIdx.x;
    const int tx  = tid & 15;
    const int ty  = tid >> 4;
    const int row0 = blockIdx.x * 64;

    float acc[4][4];
#pragma unroll
    for (int i = 0; i < 4; i++)
#pragma unroll
        for (int j = 0; j < 4; j++) acc[i][j] = 0.f;

    for (int kc = 0; kc < NF; kc += 64) {
#pragma unroll
        for (int it = 0; it < 4; it++) {
            int i = tid + it * 256;
            int r = i >> 4, q = (i & 15) << 2;
            int row = row0 + r;
            float4 v = make_float4(0.f, 0.f, 0.f, 0.f);
            if (row < n_nodes)
                v = *reinterpret_cast<const float4*>(&x[(size_t)row * NF + kc + q]);
            *reinterpret_cast<float4*>(&xs[r * TS + q]) = v;
        }
#pragma unroll
        for (int it = 0; it < 4; it++) {
            int i = tid + it * 256;
            int k = i >> 4, q = (i & 15) << 2;
            *reinterpret_cast<float4*>(&Ws[k * TS + q]) =
                *reinterpret_cast<const float4*>(&W[(size_t)(kc + k) * NH + q]);
        }
        __syncthreads();

#pragma unroll
        for (int k4 = 0; k4 < 16; k4++) {
            const int kb = k4 * 4;
            float4 xv0 = *reinterpret_cast<const float4*>(&xs[(ty * 4 + 0) * TS + kb]);
            float4 xv1 = *reinterpret_cast<const float4*>(&xs[(ty * 4 + 1) * TS + kb]);
            float4 xv2 = *reinterpret_cast<const float4*>(&xs[(ty * 4 + 2) * TS + kb]);
            float4 xv3 = *reinterpret_cast<const float4*>(&xs[(ty * 4 + 3) * TS + kb]);
#pragma unroll
            for (int kk = 0; kk < 4; kk++) {
                float4 wv = *reinterpret_cast<const float4*>(&Ws[(kb + kk) * TS + (tx << 2)]);
                float x0 = (&xv0.x)[kk];
                float x1 = (&xv1.x)[kk];
                float x2 = (&xv2.x)[kk];
                float x3 = (&xv3.x)[kk];
                acc[0][0] = fmaf(x0, wv.x, acc[0][0]); acc[0][1] = fmaf(x0, wv.y, acc[0][1]);
                acc[0][2] = fmaf(x0, wv.z, acc[0][2]); acc[0][3] = fmaf(x0, wv.w, acc[0][3]);
                acc[1][0] = fmaf(x1, wv.x, acc[1][0]); acc[1][1] = fmaf(x1, wv.y, acc[1][1]);
                acc[1][2] = fmaf(x1, wv.z, acc[1][2]); acc[1][3] = fmaf(x1, wv.w, acc[1][3]);
                acc[2][0] = fmaf(x2, wv.x, acc[2][0]); acc[2][1] = fmaf(x2, wv.y, acc[2][1]);
                acc[2][2] = fmaf(x2, wv.z, acc[2][2]); acc[2][3] = fmaf(x2, wv.w, acc[2][3]);
                acc[3][0] = fmaf(x3, wv.x, acc[3][0]); acc[3][1] = fmaf(x3, wv.y, acc[3][1]);
                acc[3][2] = fmaf(x3, wv.z, acc[3][2]); acc[3][3] = fmaf(x3, wv.w, acc[3][3]);
            }
        }
        __syncthreads();
    }

    const float4 a1 = *reinterpret_cast<const float4*>(&aw[tx << 2]);
    const float4 a2 = *reinterpret_cast<const float4*>(&aw[NH + (tx << 2)]);

#pragma unroll
    for (int i = 0; i < 4; i++) {
        int row = row0 + (ty << 2) + i;
        float sd = acc[i][0] * a1.x + acc[i][1] * a1.y + acc[i][2] * a1.z + acc[i][3] * a1.w;
        float ss = acc[i][0] * a2.x + acc[i][1] * a2.y + acc[i][2] * a2.z + acc[i][3] * a2.w;
#pragma unroll
        for (int off = 8; off; off >>= 1) {
            sd += __shfl_down_sync(0xffffffffu, sd, off, 16);
            ss += __shfl_down_sync(0xffffffffu, ss, off, 16);
        }
        if (row < n_nodes) {
            __half2 hp[2];
            hp[0] = __floats2half2_rn(acc[i][0], acc[i][1]);
            hp[1] = __floats2half2_rn(acc[i][2], acc[i][3]);
            *reinterpret_cast<float2*>(&g_zh[(size_t)row * 32 + (tx << 1)]) =
                *reinterpret_cast<const float2*>(hp);
            if (tx == 0) { g_sd[row] = sd; g_ss[row] = ss; }
        }
    }
}

// ---------------------------------------------------------------------------
__global__ void edge_scatter_kernel(const float* __restrict__ ab, int E) {
    int e = blockIdx.x * blockDim.x + threadIdx.x;
    if (e >= E) return;
    int d = g_dst[e], s = g_src[e];
    float h = g_sd[d] + g_ss[s] + __ldg(ab);
    h = (h >= 0.f) ? h : 0.05f * h;
    h = expf(h);
    int pos = atomicAdd(&g_cursor[d], 1);
    g_csr[pos] = make_int4(s, e, __float_as_int(h), 0);
}

// ---------------------------------------------------------------------------
// One warp per dst node, z gathered as half2.
__global__ void __launch_bounds__(256) aggregate_csr_kernel(
    float* __restrict__ out, float* __restrict__ alpha, int n_nodes)
{
    int w = (blockIdx.x * 256 + threadIdx.x) >> 5;
    int lane = threadIdx.x & 31;
    if (w >= n_nodes) return;

    int start = g_rowstart[w];
    int deg   = g_cnt[w];

    float2 acc = make_float2(0.f, 0.f);
    float hs = 0.f;
    for (int e = 0; e < deg; e++) {
        int4 ent = g_csr[start + e];            // broadcast, 1 sector
        float h = __int_as_float(ent.z);
        hs += h;
        __half2 zh = g_zh[(size_t)ent.x * 32 + lane];
        float2 zv = __half22float2(zh);
        acc.x = fmaf(h, zv.x, acc.x);
        acc.y = fmaf(h, zv.y, acc.y);
    }
    float inv = (hs != 0.f) ? (1.f / hs) : 0.f;
    *reinterpret_cast<float2*>(&out[(size_t)w * NH + lane * 2]) =
        make_float2(acc.x * inv, acc.y * inv);

    for (int e = lane; e < deg; e += 32) {
        int4 ent = g_csr[start + e];            // L1 hit
        alpha[ent.y] = __int_as_float(ent.z) * inv;
    }
}

// ---------------------------------------------------------------------------
extern "C" void kernel_launch(void* const* d_in, const int* in_sizes, int n_in,
                              void* d_out, int out_size)
{
    const float* x  = (const float*)d_in[0];
    const void*  ei = d_in[1];
    const float* W  = (const float*)d_in[2];
    const float* aw = (const float*)d_in[3];
    const float* ab = (const float*)d_in[4];

    const int n_nodes = in_sizes[0] / NF;
    const int E       = in_sizes[1] / 2;
    const int nb      = (n_nodes + 255) / 256;

    float* out   = (float*)d_out;
    float* alpha = out + (size_t)n_nodes * NH;

    zero_kernel<<<(n_nodes + 1023) / 1024, 1024>>>(n_nodes);
    detect_kernel<<<1, 256>>>((const int*)ei, in_sizes[1]);
    convert_kernel<<<(E / 4 + 255) / 256, 256>>>(ei, E);

    gemm_kernel<<<(n_nodes + 63) / 64, 256>>>(x, W, aw, n_nodes);

    scanA<<<nb, 256>>>(n_nodes);
    scanB<<<1, 256>>>(nb);
    scanC<<<nb, 256>>>(n_nodes);

    edge_scatter_kernel<<<(E + 255) / 256, 256>>>(ab, E);

    long long tot = (long long)n_nodes * 32;
    aggregate_csr_kernel<<<(int)((tot + 255) / 256), 256>>>(out, alpha, n_nodes);
}

// round 13
// speedup vs baseline: 1.1341x; 1.1087x over previous
#include <cuda_runtime.h>
#include <cuda_fp16.h>
#include <cstdint>

#define NF 128
#define NH 64
#define MAXN 50000
#define MAXE 800000

// Scratch (allocation-free rule: __device__ globals)
__device__ __half2 g_zh[(size_t)MAXN * (NH / 2)];   // 6.4 MB, z in fp16
__device__ float g_sd[MAXN];
__device__ float g_ss[MAXN];
__device__ int   g_dst[MAXE];
__device__ int   g_src[MAXE];
__device__ int   g_cnt[MAXN];
__device__ int   g_rowstart[MAXN];
__device__ int   g_cursor[MAXN];
__device__ int   g_bsum[1024];
__device__ int4  g_csr[MAXE];              // {src, eidx, h_bits, 0}
__device__ int   g_is32;

// ---------------------------------------------------------------------------
__global__ void zero_kernel(int n_nodes) {
    int i = blockIdx.x * blockDim.x + threadIdx.x;
    if (i < n_nodes) g_cnt[i] = 0;
    if (i == 0) g_is32 = 0;
}

// dtype probe: scan first 4096 odd words; int64 (<2^31 values) -> all zero.
__global__ void detect_kernel(const int* __restrict__ w, int nelem) {
    int found = 0;
    int lim = nelem / 2;
    if (lim > 4096) lim = 4096;
    for (int i = threadIdx.x; i < lim; i += 256)
        found |= w[2 * i + 1];
    if (__syncthreads_or(found) && threadIdx.x == 0) g_is32 = 1;
}

// Convert to int32 + histogram, 4 edges per thread, vector loads/stores.
__global__ void convert_kernel(const void* __restrict__ ei, int E) {
    int t = blockIdx.x * blockDim.x + threadIdx.x;
    int base = t * 4;
    if (base >= E) return;
    if (base + 3 < E && (E & 3) == 0) {
        int4 d4, s4;
        if (g_is32) {
            const int4* p = (const int4*)ei;
            d4 = p[base >> 2];
            s4 = p[(E + base) >> 2];
        } else {
            const longlong2* p = (const longlong2*)ei;
            longlong2 a0 = p[(base >> 1)];
            longlong2 a1 = p[(base >> 1) + 1];
            longlong2 b0 = p[((E + base) >> 1)];
            longlong2 b1 = p[((E + base) >> 1) + 1];
            d4 = make_int4((int)a0.x, (int)a0.y, (int)a1.x, (int)a1.y);
            s4 = make_int4((int)b0.x, (int)b0.y, (int)b1.x, (int)b1.y);
        }
        *reinterpret_cast<int4*>(&g_dst[base]) = d4;
        *reinterpret_cast<int4*>(&g_src[base]) = s4;
        atomicAdd(&g_cnt[d4.x], 1);
        atomicAdd(&g_cnt[d4.y], 1);
        atomicAdd(&g_cnt[d4.z], 1);
        atomicAdd(&g_cnt[d4.w], 1);
    } else {
        for (int i = base; i < E && i < base + 4; i++) {
            int d, s;
            if (g_is32) {
                const int* p = (const int*)ei;
                d = p[i]; s = p[E + i];
            } else {
                const long long* p = (const long long*)ei;
                d = (int)p[i]; s = (int)p[E + i];
            }
            g_dst[i] = d;
            g_src[i] = s;
            atomicAdd(&g_cnt[d], 1);
        }
    }
}

// ---------------------------------------------------------------------------
// Exclusive scan of g_cnt -> g_rowstart.
__global__ void scanA(int n) {
    __shared__ int s[256];
    int t = threadIdx.x, i = blockIdx.x * 256 + t;
    s[t] = (i < n) ? g_cnt[i] : 0;
    __syncthreads();
    for (int off = 128; off; off >>= 1) {
        if (t < off) s[t] += s[t + off];
        __syncthreads();
    }
    if (t == 0) g_bsum[blockIdx.x] = s[0];
}

__global__ void scanB(int nb) {
    __shared__ int s[256];
    int t = threadIdx.x;
    int v = (t < nb) ? g_bsum[t] : 0;
    s[t] = v; __syncthreads();
    for (int off = 1; off < 256; off <<= 1) {
        int a = (t >= off) ? s[t - off] : 0;
        __syncthreads();
        s[t] += a;
        __syncthreads();
    }
    if (t < nb) g_bsum[t] = s[t] - v;
}

__global__ void scanC(int n) {
    __shared__ int s[256];
    int t = threadIdx.x, i = blockIdx.x * 256 + t;
    int v = (i < n) ? g_cnt[i] : 0;
    s[t] = v; __syncthreads();
    for (int off = 1; off < 256; off <<= 1) {
        int a = (t >= off) ? s[t - off] : 0;
        __syncthreads();
        s[t] += a;
        __syncthreads();
    }
    if (i < n) {
        int start = g_bsum[blockIdx.x] + s[t] - v;
        g_rowstart[i] = start;
        g_cursor[i]   = start;
    }
}

// ---------------------------------------------------------------------------
// Register-tiled GEMM (proven config): 64x64 tile, 4x4 per thread,
// fused score reduction; z stored as fp16 half2.
__global__ void __launch_bounds__(256) gemm_kernel(
    const float* __restrict__ x, const float* __restrict__ W,
    const float* __restrict__ aw, int n_nodes)
{
    __shared__ float xs[64][64];
    __shared__ float Ws[64][64];

    const int tid = threadIdx.x;
    const int tx  = tid & 15;
    const int ty  = tid >> 4;
    const int row0 = blockIdx.x * 64;

    float acc[4][4];
#pragma unroll
    for (int i = 0; i < 4; i++)
#pragma unroll
        for (int j = 0; j < 4; j++) acc[i][j] = 0.f;

    for (int kc = 0; kc < NF; kc += 64) {
#pragma unroll
        for (int it = 0; it < 4; it++) {
            int i = tid + it * 256;
            int r = i >> 4, q = (i & 15) << 2;
            int row = row0 + r;
            float4 v = make_float4(0.f, 0.f, 0.f, 0.f);
            if (row < n_nodes)
                v = *reinterpret_cast<const float4*>(&x[(size_t)row * NF + kc + q]);
            *reinterpret_cast<float4*>(&xs[r][q]) = v;
        }
#pragma unroll
        for (int it = 0; it < 4; it++) {
            int i = tid + it * 256;
            int k = i >> 4, q = (i & 15) << 2;
            *reinterpret_cast<float4*>(&Ws[k][q]) =
                *reinterpret_cast<const float4*>(&W[(size_t)(kc + k) * NH + q]);
        }
        __syncthreads();

#pragma unroll
        for (int k = 0; k < 64; k++) {
            float4 wv = *reinterpret_cast<const float4*>(&Ws[k][tx << 2]);
            float x0 = xs[(ty << 2) + 0][k];
            float x1 = xs[(ty << 2) + 1][k];
            float x2 = xs[(ty << 2) + 2][k];
            float x3 = xs[(ty << 2) + 3][k];
            acc[0][0] = fmaf(x0, wv.x, acc[0][0]); acc[0][1] = fmaf(x0, wv.y, acc[0][1]);
            acc[0][2] = fmaf(x0, wv.z, acc[0][2]); acc[0][3] = fmaf(x0, wv.w, acc[0][3]);
            acc[1][0] = fmaf(x1, wv.x, acc[1][0]); acc[1][1] = fmaf(x1, wv.y, acc[1][1]);
            acc[1][2] = fmaf(x1, wv.z, acc[1][2]); acc[1][3] = fmaf(x1, wv.w, acc[1][3]);
            acc[2][0] = fmaf(x2, wv.x, acc[2][0]); acc[2][1] = fmaf(x2, wv.y, acc[2][1]);
            acc[2][2] = fmaf(x2, wv.z, acc[2][2]); acc[2][3] = fmaf(x2, wv.w, acc[2][3]);
            acc[3][0] = fmaf(x3, wv.x, acc[3][0]); acc[3][1] = fmaf(x3, wv.y, acc[3][1]);
            acc[3][2] = fmaf(x3, wv.z, acc[3][2]); acc[3][3] = fmaf(x3, wv.w, acc[3][3]);
        }
        __syncthreads();
    }

    const float4 a1 = *reinterpret_cast<const float4*>(&aw[tx << 2]);
    const float4 a2 = *reinterpret_cast<const float4*>(&aw[NH + (tx << 2)]);

#pragma unroll
    for (int i = 0; i < 4; i++) {
        int row = row0 + (ty << 2) + i;
        float sd = acc[i][0] * a1.x + acc[i][1] * a1.y + acc[i][2] * a1.z + acc[i][3] * a1.w;
        float ss = acc[i][0] * a2.x + acc[i][1] * a2.y + acc[i][2] * a2.z + acc[i][3] * a2.w;
#pragma unroll
        for (int off = 8; off; off >>= 1) {
            sd += __shfl_down_sync(0xffffffffu, sd, off, 16);
            ss += __shfl_down_sync(0xffffffffu, ss, off, 16);
        }
        if (row < n_nodes) {
            __half2 hp[2];
            hp[0] = __floats2half2_rn(acc[i][0], acc[i][1]);
            hp[1] = __floats2half2_rn(acc[i][2], acc[i][3]);
            *reinterpret_cast<float2*>(&g_zh[(size_t)row * 32 + (tx << 1)]) =
                *reinterpret_cast<const float2*>(hp);
            if (tx == 0) { g_sd[row] = sd; g_ss[row] = ss; }
        }
    }
}

// ---------------------------------------------------------------------------
__global__ void edge_scatter_kernel(const float* __restrict__ ab, int E) {
    int e = blockIdx.x * blockDim.x + threadIdx.x;
    if (e >= E) return;
    int d = g_dst[e], s = g_src[e];
    float h = g_sd[d] + g_ss[s] + __ldg(ab);
    h = (h >= 0.f) ? h : 0.05f * h;
    h = expf(h);
    int pos = atomicAdd(&g_cursor[d], 1);
    g_csr[pos] = make_int4(s, e, __float_as_int(h), 0);
}

// ---------------------------------------------------------------------------
// One warp per dst node, z gathered as half2.
__global__ void __launch_bounds__(256) aggregate_csr_kernel(
    float* __restrict__ out, float* __restrict__ alpha, int n_nodes)
{
    int w = (blockIdx.x * 256 + threadIdx.x) >> 5;
    int lane = threadIdx.x & 31;
    if (w >= n_nodes) return;

    int start = g_rowstart[w];
    int deg   = g_cnt[w];

    float2 acc = make_float2(0.f, 0.f);
    float hs = 0.f;
    for (int e = 0; e < deg; e++) {
        int4 ent = g_csr[start + e];            // broadcast, 1 sector
        float h = __int_as_float(ent.z);
        hs += h;
        __half2 zh = g_zh[(size_t)ent.x * 32 + lane];
        float2 zv = __half22float2(zh);
        acc.x = fmaf(h, zv.x, acc.x);
        acc.y = fmaf(h, zv.y, acc.y);
    }
    float inv = (hs != 0.f) ? (1.f / hs) : 0.f;
    *reinterpret_cast<float2*>(&out[(size_t)w * NH + lane * 2]) =
        make_float2(acc.x * inv, acc.y * inv);

    for (int e = lane; e < deg; e += 32) {
        int4 ent = g_csr[start + e];            // L1 hit
        alpha[ent.y] = __int_as_float(ent.z) * inv;
    }
}

// ---------------------------------------------------------------------------
extern "C" void kernel_launch(void* const* d_in, const int* in_sizes, int n_in,
                              void* d_out, int out_size)
{
    const float* x  = (const float*)d_in[0];
    const void*  ei = d_in[1];
    const float* W  = (const float*)d_in[2];
    const float* aw = (const float*)d_in[3];
    const float* ab = (const float*)d_in[4];

    const int n_nodes = in_sizes[0] / NF;
    const int E       = in_sizes[1] / 2;
    const int nb      = (n_nodes + 255) / 256;

    float* out   = (float*)d_out;
    float* alpha = out + (size_t)n_nodes * NH;

    // One-time side stream + fork/join events (first call = correctness run,
    // not captured; replays use the captured graph, not these API calls).
    static cudaStream_t s_side = nullptr;
    static cudaEvent_t  ev_fork = nullptr, ev_join = nullptr;
    if (!s_side) {
        cudaStreamCreateWithFlags(&s_side, cudaStreamNonBlocking);
        cudaEventCreateWithFlags(&ev_fork, cudaEventDisableTiming);
        cudaEventCreateWithFlags(&ev_join, cudaEventDisableTiming);
    }

    // Fork: gemm (independent of edge preprocessing) on the side stream.
    cudaEventRecord(ev_fork, (cudaStream_t)0);
    cudaStreamWaitEvent(s_side, ev_fork, 0);
    gemm_kernel<<<(n_nodes + 63) / 64, 256, 0, s_side>>>(x, W, aw, n_nodes);
    cudaEventRecord(ev_join, s_side);

    // Main stream: edge-index preprocessing chain, overlapped with gemm.
    zero_kernel<<<(n_nodes + 1023) / 1024, 1024>>>(n_nodes);
    detect_kernel<<<1, 256>>>((const int*)ei, in_sizes[1]);
    convert_kernel<<<(E / 4 + 255) / 256, 256>>>(ei, E);
    scanA<<<nb, 256>>>(n_nodes);
    scanB<<<1, 256>>>(nb);
    scanC<<<nb, 256>>>(n_nodes);

    // Join: scatter needs both gemm (sd/ss) and the scan chain (cursor).
    cudaStreamWaitEvent((cudaStream_t)0, ev_join, 0);

    edge_scatter_kernel<<<(E + 255) / 256, 256>>>(ab, E);

    long long tot = (long long)n_nodes * 32;
    aggregate_csr_kernel<<<(int)((tot + 255) / 256), 256>>>(out, alpha, n_nodes);
}